// round 17
// baseline (speedup 1.0000x reference)
#include <cuda_runtime.h>
#include <cuda_fp16.h>
#include <cstddef>
#include <cstdint>

// SparseConv: out[out_map[k,m]] += x[in_map[k,m]] @ W[k]   (K=27, M=65536, Cin=Cout=64)
//
// Round 17: R16 (fp16 m16n8k16, 197.2us) + double-buffered cp.async gather.
//   fp16 A tile is 18.4KB -> two buffers + B = 46KB, occ 3 kept, 128-edge tiles kept.
//   Pipeline: issue g(t+1) -> wait_group 1 (g(t) landed during prior tile) -> MMA(t)
//   -> RED epilogue -> sync. Removes the ~600cyc per-tile cp.async exposure that
//   had issue at 11.7%.

#define CIN     64
#define COUT    64
#define THREADS 256
#define CTAS_X  16

#define STRIDE_A 144                 // bytes per A row (64 halves = 128B + 16B pad)
#define STRIDE_B 144

#define ABUF     (128 * STRIDE_A)    // 18432 B per A buffer
#define SM_A0    0
#define SM_A1    ABUF                // 18432
#define SM_B     (2 * ABUF)          // 36864
#define SM_TOTAL (SM_B + 64 * STRIDE_B)  // 46080 B -> 3 CTAs/SM

// global scratch: fp16 copy of x (128 B per row)
#define NMAX_HALF (262144 * 64)
__device__ __align__(16) __half g_xh[NMAX_HALF];

__device__ __forceinline__ uint32_t smem_u32(const void* p) {
    uint32_t a;
    asm("{ .reg .u64 t; cvta.to.shared.u64 t, %1; cvt.u32.u64 %0, t; }" : "=r"(a) : "l"(p));
    return a;
}

#define CP_ASYNC16(dst, src) \
    asm volatile("cp.async.cg.shared.global [%0], [%1], 16;" :: "r"(dst), "l"(src) : "memory")
#define CP_COMMIT()  asm volatile("cp.async.commit_group;" ::: "memory")
#define CP_WAIT0()   asm volatile("cp.async.wait_group 0;" ::: "memory")
#define CP_WAIT1()   asm volatile("cp.async.wait_group 1;" ::: "memory")

#define LDSM_X4(r, addr) \
    asm volatile("ldmatrix.sync.aligned.m8n8.x4.shared.b16 {%0,%1,%2,%3}, [%4];" \
        : "=r"((r)[0]), "=r"((r)[1]), "=r"((r)[2]), "=r"((r)[3]) : "r"(addr))

#define LDSM_X4_T(r, addr) \
    asm volatile("ldmatrix.sync.aligned.m8n8.x4.trans.shared.b16 {%0,%1,%2,%3}, [%4];" \
        : "=r"((r)[0]), "=r"((r)[1]), "=r"((r)[2]), "=r"((r)[3]) : "r"(addr))

#define MMA_F16(c, a, b0, b1) \
    asm volatile("mma.sync.aligned.m16n8k16.row.col.f32.f16.f16.f32 " \
        "{%0,%1,%2,%3}, {%4,%5,%6,%7}, {%8,%9}, {%0,%1,%2,%3};" \
        : "+f"((c)[0]), "+f"((c)[1]), "+f"((c)[2]), "+f"((c)[3]) \
        : "r"((a)[0]), "r"((a)[1]), "r"((a)[2]), "r"((a)[3]), "r"(b0), "r"(b1))

__device__ __forceinline__ void red_add_v4(float* dst, float a, float b, float c, float d) {
    asm volatile("red.global.add.v4.f32 [%0], {%1, %2, %3, %4};"
                 :: "l"(dst), "f"(a), "f"(b), "f"(c), "f"(d) : "memory");
}

// ---------- prep: zero out + convert x fp32 -> fp16 (one launch) ----------
__global__ void __launch_bounds__(256) prep_kernel(
    const float* __restrict__ x, float* __restrict__ out, int total8, int out4)
{
    const int i = blockIdx.x * 256 + threadIdx.x;
    if (i < out4) ((float4*)out)[i] = make_float4(0.f, 0.f, 0.f, 0.f);
    if (i < total8) {
        const float4 v0 = ((const float4*)x)[2 * i];
        const float4 v1 = ((const float4*)x)[2 * i + 1];
        const __half2 h0 = __floats2half2_rn(v0.x, v0.y);
        const __half2 h1 = __floats2half2_rn(v0.z, v0.w);
        const __half2 h2 = __floats2half2_rn(v1.x, v1.y);
        const __half2 h3 = __floats2half2_rn(v1.z, v1.w);
        uint4 o;
        o.x = *(const uint32_t*)&h0;
        o.y = *(const uint32_t*)&h1;
        o.z = *(const uint32_t*)&h2;
        o.w = *(const uint32_t*)&h3;
        ((uint4*)g_xh)[i] = o;
    }
}

// issue one 128-edge tile gather into A buffer `b` (4 cp.async/thread) + commit
__device__ __forceinline__ void gather_f16(
    uint32_t sb, int b, const int* __restrict__ in_map, int base, int tid)
{
    const char* xhB = (const char*)g_xh;
    const uint32_t dA = sb + (uint32_t)(b * ABUF);
    #pragma unroll
    for (int j = 0; j < 4; j++) {
        const int f = tid + j * THREADS;
        const int e = f >> 3, c = f & 7;
        const int row = in_map[base + e];
        CP_ASYNC16(dA + (uint32_t)(e * STRIDE_A + c * 16),
                   xhB + (size_t)row * 128 + c * 16);
    }
    CP_COMMIT();
}

// ---------- main kernel ----------
__global__ void __launch_bounds__(THREADS, 3) sparse_conv_f16p(
    const float* __restrict__ W,
    const int*   __restrict__ in_map,
    const int*   __restrict__ out_map,
    float*       __restrict__ out,
    int M)
{
    extern __shared__ char smem[];
    const uint32_t sb = smem_u32(smem);
    const int tid  = threadIdx.x;
    const int w    = tid >> 5;
    const int lane = tid & 31;
    const int mg   = w >> 1;        // rows 32*mg .. 32*mg+31
    const int nh   = w & 1;         // cols 32*nh .. 32*nh+31
    const int k    = blockIdx.y;
    const int kM   = k * M;
    const int ntiles = M >> 7;

    // --- stage W[k] -> fp16 in smem, [cin][cout] rows, 144B stride ---
    {
        const float* Wk = W + (size_t)k * (CIN * COUT);
        #pragma unroll
        for (int i = 0; i < (CIN * COUT) / THREADS; i++) {
            const int lin = tid + i * THREADS;
            const int c = lin >> 6, n = lin & 63;
            *(__half*)(smem + SM_B + (uint32_t)(c * STRIDE_B + n * 2)) =
                __float2half_rn(Wk[lin]);
        }
    }

    // fragment addressing
    const uint32_t b_off = (uint32_t)((lane & 15) * STRIDE_B + (lane >> 4) * 16 + nh * 64);
    const uint32_t bB = sb + SM_B + b_off;
    const uint32_t a_off = (uint32_t)((32 * mg + (lane & 15)) * STRIDE_A + (lane >> 4) * 16);

    // epilogue lane mapping
    const bool odd = (lane & 1);
    const int  er0 = 32 * mg + (lane >> 2) + (odd ? 8 : 0);
    const int  q0  = (lane & 2) * 2;

    // --- prologue: issue first gather into buf 0 ---
    int mt = blockIdx.x;
    gather_f16(sb, 0, in_map, kM + (mt << 7), tid);
    int buf = 0;

    while (mt < ntiles) {
        const int nxt = mt + CTAS_X;
        const int m0 = mt << 7;

        // epilogue rows (LDG in flight through wait + MMA)
        const int orow0 = out_map[kM + m0 + er0];
        const int orow1 = out_map[kM + m0 + er0 + 16];

        // issue next tile's gather into other buffer, then wait only for THIS tile's
        if (nxt < ntiles) {
            gather_f16(sb, buf ^ 1, in_map, kM + (nxt << 7), tid);
            CP_WAIT1();
        } else {
            CP_WAIT0();
        }
        __syncthreads();   // group(mt) visible CTA-wide (also orders W staging, iter 0)

        // --- MMA: 4 k-steps x 2 m-tiles x 4 n8-tiles = 32 mma/warp ---
        float acc[2][4][4];
        #pragma unroll
        for (int t = 0; t < 2; t++)
            #pragma unroll
            for (int j = 0; j < 4; j++)
                #pragma unroll
                for (int i = 0; i < 4; i++) acc[t][j][i] = 0.0f;

        const uint32_t aB = sb + (uint32_t)(buf * ABUF) + a_off;
        #pragma unroll
        for (int s = 0; s < 4; s++) {
            uint32_t bh[2][4];
            const uint32_t so = (uint32_t)(s * 16 * STRIDE_B);
            LDSM_X4_T(bh[0], bB + so);
            LDSM_X4_T(bh[1], bB + so + 32);
            #pragma unroll
            for (int t = 0; t < 2; t++) {
                uint32_t ah[4];
                LDSM_X4(ah, aB + (uint32_t)(t * 16 * STRIDE_A + s * 32));
                #pragma unroll
                for (int p = 0; p < 2; p++) {
                    MMA_F16(acc[t][2 * p],     ah, bh[p][0], bh[p][1]);
                    MMA_F16(acc[t][2 * p + 1], ah, bh[p][2], bh[p][3]);
                }
            }
        }

        // --- epilogue: shfl pair-swap -> red.global.add.v4 ---
        #pragma unroll
        for (int t = 0; t < 2; t++) {
            const int orow = t ? orow1 : orow0;
            float* obase = out + (size_t)orow * COUT + nh * 32 + q0;
            #pragma unroll
            for (int j = 0; j < 4; j++) {
                float* c = acc[t][j];
                const float s0 = __shfl_xor_sync(0xFFFFFFFFu, c[0], 1);
                const float s1 = __shfl_xor_sync(0xFFFFFFFFu, c[1], 1);
                const float s2 = __shfl_xor_sync(0xFFFFFFFFu, c[2], 1);
                const float s3 = __shfl_xor_sync(0xFFFFFFFFu, c[3], 1);
                const float v0 = odd ? s2 : c[0];
                const float v1 = odd ? s3 : c[1];
                const float v2 = odd ? c[2] : s0;
                const float v3 = odd ? c[3] : s1;
                red_add_v4(obase + 8 * j, v0, v1, v2, v3);
            }
        }

        __syncthreads();   // all warps' LDSM of buf done before it is re-gathered (t+2)
        mt = nxt;
        buf ^= 1;
    }
}

extern "C" void kernel_launch(void* const* d_in, const int* in_sizes, int n_in,
                              void* d_out, int out_size)
{
    const float* x       = (const float*)d_in[0];
    const float* W       = (const float*)d_in[1];
    const int*   in_map  = (const int*)d_in[2];
    const int*   out_map = (const int*)d_in[3];
    float*       out     = (float*)d_out;

    const int K = in_sizes[1] / (CIN * COUT);   // 27
    const int M = in_sizes[2] / K;              // 65536
    const int total8 = in_sizes[0] / 8;
    const int out4   = out_size / 4;
    const int pmax   = total8 > out4 ? total8 : out4;

    static bool attr_set = false;
    if (!attr_set) {
        cudaFuncSetAttribute(sparse_conv_f16p,
                             cudaFuncAttributeMaxDynamicSharedMemorySize, SM_TOTAL);
        attr_set = true;
    }

    prep_kernel<<<(pmax + 255) / 256, 256>>>(x, out, total8, out4);

    dim3 grid(CTAS_X, K);
    sparse_conv_f16p<<<grid, THREADS, SM_TOTAL>>>(W, in_map, out_map, out, M);
}